// round 5
// baseline (speedup 1.0000x reference)
#include <cuda_runtime.h>
#include <cuda_bf16.h>
#include <cstdint>

#define NWARPS    4
#define NTHREADS  (NWARPS * 32)
#define TM        (NWARPS * 16)      // 64 rows per CTA
#define PW        152                // wide pitch (holds up to 144 cols)
#define PQ        88                 // narrow pitch (holds up to 80 cols)
#define WSZ       (16*PW + 16*PW + 16*PQ)   // per-warp smem floats: P, C, Q

// Packed B-fragment weights: per (layer, ktile, ntile, lane) a float4
// {Whi[k0+t][n0+g], Whi[k0+4+t][n0+g], Wlo[...], Wlo[...]}.
// Total blocks = 1024, floats = 1024*32*4 = 131072 (524 KB).
__device__ float g_wpacked[131072];

// Layer table: K, N, packed float offset, cumulative block count
__constant__ int c_lK[9]   = {64,64,64,80,80,80,144,144,64};
__constant__ int c_lN[9]   = {64,64,64,80,80,80,144, 64,64};
__constant__ int c_loff[9] = {0,8192,16384,24576,37376,50176,62976,104448,122880};
__constant__ int c_lcum[10]= {0,64,128,192,292,392,492,816,960,1024};

// Epilogue segment descriptors (31 segments of 8 after the 64 hb outputs)
__constant__ int c_kind[31] = {3,0,2,2,2,2,2,0,0,0,0,0,6,6,6,6,0,1,5,6,1,0,5,4,0,6,6,6,6,6,6};
__constant__ int c_col[31]  = {18,20,22,23,24,25,26,27,28,29,30,31,0,1,2,3,35,36,37,4,32,33,34,19,38,5,6,7,8,9,10};
__constant__ int c_scol[11] = {40,41,42,43,39,44,45,46,47,48,49};
__constant__ int c_widx[11] = {0,2,3,5,1,4,4,4,4,4,4};

struct Params {
    const float *state;
    const float *suit, *rank;
    const float *hW1,*hb1,*hW2,*hb2,*hW3,*hb3;
    const float *bW1,*bb1,*bW2,*bb2,*bW3,*bb3;
    const float *cW1,*cb1,*cW2,*cb2,*cW3,*cb3;
    const float *pos,*action,*active,*street,*nump,*blind;
    const float *sW,*sb;
    float *out;
    int nrows;
};

__device__ __forceinline__ float leaky(float v) { return v > 0.0f ? v : 0.01f * v; }

__device__ __forceinline__ uint32_t f2t(float x) {
    uint32_t r;
    asm("cvt.rna.tf32.f32 %0, %1;" : "=r"(r) : "f"(x));
    return r;
}
__device__ __forceinline__ float tf32f(float x) { return __uint_as_float(f2t(x)); }

__device__ __forceinline__ void mma_acc(float (&c)[4],
                                        uint32_t a0, uint32_t a1, uint32_t a2, uint32_t a3,
                                        uint32_t b0, uint32_t b1)
{
    asm volatile("mma.sync.aligned.m16n8k8.row.col.f32.tf32.tf32.f32 "
                 "{%0,%1,%2,%3}, {%4,%5,%6,%7}, {%8,%9}, {%0,%1,%2,%3};\n"
                 : "+f"(c[0]), "+f"(c[1]), "+f"(c[2]), "+f"(c[3])
                 : "r"(a0), "r"(a1), "r"(a2), "r"(a3), "r"(b0), "r"(b1));
}

// ---------------- weight packing kernel (runs once per launch) ----------------
__global__ void pack_kernel(Params p)
{
    int tid = blockIdx.x * blockDim.x + threadIdx.x;
    int bid = tid >> 5, lane = tid & 31;
    if (bid >= 1024) return;
    int l = 0;
    while (bid >= c_lcum[l + 1]) l++;
    int K = c_lK[l], N = c_lN[l];
    int NT = N >> 3;
    int b = bid - c_lcum[l];
    int kt = b / NT;
    int g = lane >> 2, t = lane & 3;
    int nt = b - kt * NT;
    const float* W;
    switch (l) {
        case 0: W = p.hW1; break;  case 1: W = p.hW2; break;  case 2: W = p.hW3; break;
        case 3: W = p.bW1; break;  case 4: W = p.bW2; break;  case 5: W = p.bW3; break;
        case 6: W = p.cW1; break;  case 7: W = p.cW2; break;  default: W = p.cW3; break;
    }
    int k0 = kt * 8, n0 = nt * 8;
    float w0 = W[(k0 + t) * N + n0 + g];
    float w1 = W[(k0 + 4 + t) * N + n0 + g];
    float h0 = tf32f(w0), h1 = tf32f(w1);
    float4 v = make_float4(h0, h1, tf32f(w0 - h0), tf32f(w1 - h1));
    ((float4*)(g_wpacked + c_loff[l]))[(size_t)b * 32 + lane] = v;
    (void)K;
}

// ---------------- dense layer: 16 warp-private rows, 3xTF32 ----------------
template <int NIN, int NOUT, bool ACT>
__device__ __forceinline__ void dense_layer(const float* __restrict__ Wp,
                                            const float* __restrict__ bg,
                                            const float* __restrict__ Xs, int PX,
                                            float* __restrict__ Ys, int PY,
                                            int g, int t, int lane)
{
    constexpr int NT = NOUT / 8;
    constexpr int KT = NIN / 8;

    float acc[NT][4];
#pragma unroll
    for (int nt = 0; nt < NT; nt++) {
        acc[nt][0] = 0.f; acc[nt][1] = 0.f; acc[nt][2] = 0.f; acc[nt][3] = 0.f;
    }

    const float4* wbase = (const float4*)Wp + lane;

#pragma unroll 1
    for (int kt = 0; kt < KT; kt++) {
        const float* xp = Xs + g * PX + kt * 8 + t;
        float x0 = xp[0];
        float x2 = xp[4];
        float x1 = xp[8 * PX];
        float x3 = xp[8 * PX + 4];
        uint32_t ah0 = f2t(x0), ah1 = f2t(x1), ah2 = f2t(x2), ah3 = f2t(x3);
        uint32_t al0 = f2t(x0 - __uint_as_float(ah0));
        uint32_t al1 = f2t(x1 - __uint_as_float(ah1));
        uint32_t al2 = f2t(x2 - __uint_as_float(ah2));
        uint32_t al3 = f2t(x3 - __uint_as_float(ah3));

        const float4* wp = wbase + (size_t)kt * NT * 32;
#pragma unroll
        for (int nt = 0; nt < NT; nt++) {
            float4 f = __ldg(wp + nt * 32);
            uint32_t bh0 = __float_as_uint(f.x), bh1 = __float_as_uint(f.y);
            uint32_t bl0 = __float_as_uint(f.z), bl1 = __float_as_uint(f.w);
            mma_acc(acc[nt], ah0, ah1, ah2, ah3, bh0, bh1);
            mma_acc(acc[nt], al0, al1, al2, al3, bh0, bh1);
            mma_acc(acc[nt], ah0, ah1, ah2, ah3, bl0, bl1);
        }
    }

#pragma unroll
    for (int nt = 0; nt < NT; nt++) {
        float2 bb = __ldg((const float2*)(bg + nt * 8 + 2 * t));
        float v0 = acc[nt][0] + bb.x;
        float v1 = acc[nt][1] + bb.y;
        float v2 = acc[nt][2] + bb.x;
        float v3 = acc[nt][3] + bb.y;
        if (ACT) { v0 = leaky(v0); v1 = leaky(v1); v2 = leaky(v2); v3 = leaky(v3); }
        *(float2*)(Ys + g * PY + nt * 8 + 2 * t)       = make_float2(v0, v1);
        *(float2*)(Ys + (g + 8) * PY + nt * 8 + 2 * t) = make_float2(v2, v3);
    }
    __syncwarp();
}

__global__ void __launch_bounds__(NTHREADS)
preproc_kernel(Params p)
{
    extern __shared__ float smem[];
    const int warp = threadIdx.x >> 5;
    const int lane = threadIdx.x & 31;
    const int g = lane >> 2, t = lane & 3;

    float* Pb = smem + warp * WSZ;        // 16 x 152
    float* Cb = Pb + 16 * PW;             // 16 x 152 (concat buffer)
    float* Qb = Cb + 16 * PW;             // 16 x 88

    const int row0 = blockIdx.x * TM + warp * 16;

    // ---------- hand gather -> Pb[., 0..63] ----------
#pragma unroll 1
    for (int r = 0; r < 16; r++) {
        int row = row0 + r;
        if (row >= p.nrows) continue;
        const float* st = p.state + (size_t)row * 50;
#pragma unroll
        for (int e = lane; e < 64; e += 32) {
            int cc = e >> 4, w = e & 15, d = e & 7;
            int col = (w < 8) ? (2 * cc + 1) : (2 * cc);
            int iv = (int)st[col];
            Pb[r * PW + e] = (w < 8) ? __ldg(p.suit + iv * 8 + d)
                                     : __ldg(p.rank + iv * 8 + d);
        }
    }
    __syncwarp();

    // hand MLP: P -> Q -> P -> C[0:64]
    dense_layer<64, 64, true >(g_wpacked + 0,     p.hb1, Pb, PW, Qb, PQ, g, t, lane);
    dense_layer<64, 64, true >(g_wpacked + 8192,  p.hb2, Qb, PQ, Pb, PW, g, t, lane);
    dense_layer<64, 64, false>(g_wpacked + 16384, p.hb3, Pb, PW, Cb, PW, g, t, lane);

    // ---------- board gather -> Qb[., 0..79] ----------
#pragma unroll 1
    for (int r = 0; r < 16; r++) {
        int row = row0 + r;
        if (row >= p.nrows) continue;
        const float* st = p.state + (size_t)row * 50;
#pragma unroll
        for (int e = lane; e < 80; e += 32) {
            int cc = e >> 4, w = e & 15, d = e & 7;
            int col = (w < 8) ? (9 + 2 * cc) : (8 + 2 * cc);
            int iv = (int)st[col];
            Qb[r * PQ + e] = (w < 8) ? __ldg(p.suit + iv * 8 + d)
                                     : __ldg(p.rank + iv * 8 + d);
        }
    }
    __syncwarp();

    // board MLP: Q -> P -> Q -> C[64:144]
    dense_layer<80, 80, true >(g_wpacked + 24576, p.bb1, Qb, PQ, Pb, PW, g, t, lane);
    dense_layer<80, 80, true >(g_wpacked + 37376, p.bb2, Pb, PW, Qb, PQ, g, t, lane);
    dense_layer<80, 80, false>(g_wpacked + 50176, p.bb3, Qb, PQ, Cb + 64, PW, g, t, lane);

    // hb MLP: C(144) -> P(144) -> Q(64) -> P(64)
    dense_layer<144,144, true >(g_wpacked + 62976,  p.cb1, Cb, PW, Pb, PW, g, t, lane);
    dense_layer<144, 64, true >(g_wpacked + 104448, p.cb2, Pb, PW, Qb, PQ, g, t, lane);
    dense_layer< 64, 64, false>(g_wpacked + 122880, p.cb3, Qb, PQ, Pb, PW, g, t, lane);

    // ---------- output epilogue (warp-private; no sync needed) ----------
    const float* tabs[6] = { p.pos, p.action, p.active, p.street, p.nump, p.blind };
#pragma unroll 1
    for (int r = 0; r < 16; r++) {
        int row = row0 + r;
        if (row >= p.nrows) continue;
        float* orow = p.out + (size_t)row * 312;
        const float* st = p.state + (size_t)row * 50;
        const float* Crow = Pb + r * PW;
        for (int tt = lane; tt < 312; tt += 32) {
            float v;
            if (tt < 64) {
                v = Crow[tt];
            } else {
                int s = (tt - 64) >> 3, d = (tt - 64) & 7;
                int kind = c_kind[s], col = c_col[s];
                if (kind == 6) {
                    float sc = st[c_scol[col]];
                    int w = c_widx[col];
                    v = fmaf(sc, __ldg(p.sW + w * 8 + d), __ldg(p.sb + w * 8 + d));
                } else {
                    int iv = (int)st[col];
                    v = __ldg(tabs[kind] + iv * 8 + d);
                }
            }
            orow[tt] = v;
        }
    }
}

extern "C" void kernel_launch(void* const* d_in, const int* in_sizes, int n_in,
                              void* d_out, int out_size)
{
    Params p;
    p.state  = (const float*)d_in[0];
    p.suit   = (const float*)d_in[1];
    p.rank   = (const float*)d_in[2];
    p.hW1 = (const float*)d_in[3];  p.hb1 = (const float*)d_in[4];
    p.hW2 = (const float*)d_in[5];  p.hb2 = (const float*)d_in[6];
    p.hW3 = (const float*)d_in[7];  p.hb3 = (const float*)d_in[8];
    p.bW1 = (const float*)d_in[9];  p.bb1 = (const float*)d_in[10];
    p.bW2 = (const float*)d_in[11]; p.bb2 = (const float*)d_in[12];
    p.bW3 = (const float*)d_in[13]; p.bb3 = (const float*)d_in[14];
    p.cW1 = (const float*)d_in[15]; p.cb1 = (const float*)d_in[16];
    p.cW2 = (const float*)d_in[17]; p.cb2 = (const float*)d_in[18];
    p.cW3 = (const float*)d_in[19]; p.cb3 = (const float*)d_in[20];
    p.pos    = (const float*)d_in[21];
    p.action = (const float*)d_in[22];
    p.active = (const float*)d_in[23];
    p.street = (const float*)d_in[24];
    p.nump   = (const float*)d_in[25];
    p.blind  = (const float*)d_in[26];
    p.sW     = (const float*)d_in[27];
    p.sb     = (const float*)d_in[28];
    p.out    = (float*)d_out;
    p.nrows  = out_size / 312;

    pack_kernel<<<128, 256>>>(p);

    size_t smem_bytes = (size_t)NWARPS * WSZ * sizeof(float);
    cudaFuncSetAttribute(preproc_kernel, cudaFuncAttributeMaxDynamicSharedMemorySize,
                         (int)smem_bytes);
    int grid = (p.nrows + TM - 1) / TM;
    preproc_kernel<<<grid, NTHREADS, smem_bytes>>>(p);
}

// round 6
// speedup vs baseline: 2.8107x; 2.8107x over previous
#include <cuda_runtime.h>
#include <cuda_fp16.h>
#include <cstdint>

#define NWARPS    4
#define NTHREADS  (NWARPS * 32)
#define TM        (NWARPS * 16)     // 64 rows per CTA
#define PW        146               // pitch of wide (concat) buffer, conflict-light
#define PQ        90                // pitch of narrow work buffer
#define WSZ       (16*PW + 16*PQ)   // per-warp smem floats

// Packed fp16 hi/lo B-fragments. Per (layer,kt16,nt8,lane): uint4 =
// {bh0(k=2t,2t+1), bh1(k=2t+8,2t+9), bl0, bl1} for col n0+g. 16384 uint4 = 256KB.
__device__ uint4 g_wpk[16384];

// layer tables: KT=K/16, NT=N/8, block-cumsum, uint4 offset
__constant__ int c_KT[9]   = {4,4,4,5,5,5,9,9,4};
__constant__ int c_NT[9]   = {8,8,8,10,10,10,18,8,8};
__constant__ int c_bcum[10]= {0,32,64,96,146,196,246,408,480,512};
__constant__ int c_u4off[9]= {0,1024,2048,3072,4672,6272,7872,13056,15360};

// Epilogue segment descriptors (31 segments of 8 after the 64 hb outputs)
__constant__ int c_kind[31] = {3,0,2,2,2,2,2,0,0,0,0,0,6,6,6,6,0,1,5,6,1,0,5,4,0,6,6,6,6,6,6};
__constant__ int c_col[31]  = {18,20,22,23,24,25,26,27,28,29,30,31,0,1,2,3,35,36,37,4,32,33,34,19,38,5,6,7,8,9,10};
__constant__ int c_scol[11] = {40,41,42,43,39,44,45,46,47,48,49};
__constant__ int c_widx[11] = {0,2,3,5,1,4,4,4,4,4,4};

struct Params {
    const float *state;
    const float *suit, *rank;
    const float *hW1,*hb1,*hW2,*hb2,*hW3,*hb3;
    const float *bW1,*bb1,*bW2,*bb2,*bW3,*bb3;
    const float *cW1,*cb1,*cW2,*cb2,*cW3,*cb3;
    const float *pos,*action,*active,*street,*nump,*blind;
    const float *sW,*sb;
    float *out;
    int nrows;
};

__device__ __forceinline__ float leaky(float v) { return v > 0.0f ? v : 0.01f * v; }

__device__ __forceinline__ uint32_t h2bits(__half2 h) {
    return *reinterpret_cast<uint32_t*>(&h);
}

// split (x,y) into packed fp16 hi and lo half2 bit patterns
__device__ __forceinline__ void split2(float x, float y, uint32_t& hi, uint32_t& lo) {
    __half2 h = __floats2half2_rn(x, y);
    float2 hf = __half22float2(h);
    __half2 l = __floats2half2_rn(x - hf.x, y - hf.y);
    hi = h2bits(h);
    lo = h2bits(l);
}

__device__ __forceinline__ void mma16(float (&c)[4],
                                      uint32_t a0, uint32_t a1, uint32_t a2, uint32_t a3,
                                      uint32_t b0, uint32_t b1)
{
    asm volatile("mma.sync.aligned.m16n8k16.row.col.f32.f16.f16.f32 "
                 "{%0,%1,%2,%3}, {%4,%5,%6,%7}, {%8,%9}, {%0,%1,%2,%3};\n"
                 : "+f"(c[0]), "+f"(c[1]), "+f"(c[2]), "+f"(c[3])
                 : "r"(a0), "r"(a1), "r"(a2), "r"(a3), "r"(b0), "r"(b1));
}

// ---------------- weight packing kernel (once per launch) ----------------
__global__ void pack_kernel(Params p)
{
    int tid = blockIdx.x * blockDim.x + threadIdx.x;
    if (tid >= 16384) return;
    int bid = tid >> 5, lane = tid & 31;
    int l = 0;
    while (bid >= c_bcum[l + 1]) l++;
    int NT = c_NT[l];
    int N  = NT * 8;
    int b  = bid - c_bcum[l];
    int kt = b / NT, nt = b % NT;
    int g = lane >> 2, t = lane & 3;
    const float* W;
    switch (l) {
        case 0: W = p.hW1; break;  case 1: W = p.hW2; break;  case 2: W = p.hW3; break;
        case 3: W = p.bW1; break;  case 4: W = p.bW2; break;  case 5: W = p.bW3; break;
        case 6: W = p.cW1; break;  case 7: W = p.cW2; break;  default: W = p.cW3; break;
    }
    int k0 = kt * 16, n = nt * 8 + g;
    float w00 = W[(k0 + 2*t)     * N + n];
    float w01 = W[(k0 + 2*t + 1) * N + n];
    float w10 = W[(k0 + 8 + 2*t)     * N + n];
    float w11 = W[(k0 + 8 + 2*t + 1) * N + n];
    uint4 v;
    split2(w00, w01, v.x, v.z);
    split2(w10, w11, v.y, v.w);
    g_wpk[c_u4off[l] + b * 32 + lane] = v;
}

// ---------------- dense layer: 16 warp-private rows, fp16x3 ----------------
// In-place safe (Ys may alias Xs): each lane's read addr set ⊇ its write set.
template <int NIN, int NOUT, bool ACT>
__device__ __forceinline__ void dense_layer(const uint4* Wp,
                                            const float* __restrict__ bg,
                                            const float* Xs, int PX,
                                            float* Ys, int PY,
                                            int g, int t, int lane)
{
    constexpr int NT = NOUT / 8;
    constexpr int KT = NIN / 16;

    float acc[NT][4];
#pragma unroll
    for (int nt = 0; nt < NT; nt++) {
        acc[nt][0] = 0.f; acc[nt][1] = 0.f; acc[nt][2] = 0.f; acc[nt][3] = 0.f;
    }

    const uint4* wbase = Wp + lane;

    auto body = [&](int kt) {
        const float* xp = Xs + g * PX + kt * 16 + 2 * t;
        float2 x00 = *(const float2*)(xp);              // (g,   k0+2t..+1)
        float2 x10 = *(const float2*)(xp + 8 * PX);     // (g+8, k0+2t..+1)
        float2 x01 = *(const float2*)(xp + 8);          // (g,   k0+8+2t..)
        float2 x11 = *(const float2*)(xp + 8 * PX + 8); // (g+8, ...)
        uint32_t ah0, al0, ah1, al1, ah2, al2, ah3, al3;
        split2(x00.x, x00.y, ah0, al0);
        split2(x10.x, x10.y, ah1, al1);
        split2(x01.x, x01.y, ah2, al2);
        split2(x11.x, x11.y, ah3, al3);

        const uint4* wp = wbase + (size_t)kt * NT * 32;
#pragma unroll
        for (int nt = 0; nt < NT; nt++) {
            uint4 w = __ldg(wp + nt * 32);
            mma16(acc[nt], ah0, ah1, ah2, ah3, w.x, w.y);  // Ah*Bh
            mma16(acc[nt], al0, al1, al2, al3, w.x, w.y);  // Al*Bh
            mma16(acc[nt], ah0, ah1, ah2, ah3, w.z, w.w);  // Ah*Bl
        }
    };

    if constexpr (NT <= 10) {
#pragma unroll 2
        for (int kt = 0; kt < KT; kt++) body(kt);
    } else {
#pragma unroll 1
        for (int kt = 0; kt < KT; kt++) body(kt);
    }

    __syncwarp();
#pragma unroll
    for (int nt = 0; nt < NT; nt++) {
        float2 bb = __ldg((const float2*)(bg + nt * 8 + 2 * t));
        float v0 = acc[nt][0] + bb.x;
        float v1 = acc[nt][1] + bb.y;
        float v2 = acc[nt][2] + bb.x;
        float v3 = acc[nt][3] + bb.y;
        if (ACT) { v0 = leaky(v0); v1 = leaky(v1); v2 = leaky(v2); v3 = leaky(v3); }
        *(float2*)(Ys + g * PY + nt * 8 + 2 * t)       = make_float2(v0, v1);
        *(float2*)(Ys + (g + 8) * PY + nt * 8 + 2 * t) = make_float2(v2, v3);
    }
    __syncwarp();
}

__global__ void __launch_bounds__(NTHREADS, 3)
preproc_kernel(Params p)
{
    extern __shared__ float smem[];
    const int warp = threadIdx.x >> 5;
    const int lane = threadIdx.x & 31;
    const int g = lane >> 2, t = lane & 3;

    float* Cb = smem + warp * WSZ;   // 16 x 146 (concat + hb chain, in-place)
    float* Bb = Cb + 16 * PW;        // 16 x 90  (hand/board work buffer)

    const int row0 = blockIdx.x * TM + warp * 16;

    // ---------- hand gather -> Bb[., 0..63] ----------
#pragma unroll 1
    for (int r = 0; r < 16; r++) {
        int row = row0 + r;
        if (row >= p.nrows) continue;
        const float* st = p.state + (size_t)row * 50;
#pragma unroll
        for (int e = lane; e < 64; e += 32) {
            int cc = e >> 4, w = e & 15, d = e & 7;
            int col = (w < 8) ? (2 * cc + 1) : (2 * cc);
            int iv = (int)st[col];
            Bb[r * PQ + e] = (w < 8) ? __ldg(p.suit + iv * 8 + d)
                                     : __ldg(p.rank + iv * 8 + d);
        }
    }
    __syncwarp();

    // hand MLP: B -> B -> B -> C[0:64]
    dense_layer<64, 64, true >(g_wpk + 0,    p.hb1, Bb, PQ, Bb, PQ, g, t, lane);
    dense_layer<64, 64, true >(g_wpk + 1024, p.hb2, Bb, PQ, Bb, PQ, g, t, lane);
    dense_layer<64, 64, false>(g_wpk + 2048, p.hb3, Bb, PQ, Cb, PW, g, t, lane);

    // ---------- board gather -> Bb[., 0..79] ----------
#pragma unroll 1
    for (int r = 0; r < 16; r++) {
        int row = row0 + r;
        if (row >= p.nrows) continue;
        const float* st = p.state + (size_t)row * 50;
#pragma unroll
        for (int e = lane; e < 80; e += 32) {
            int cc = e >> 4, w = e & 15, d = e & 7;
            int col = (w < 8) ? (9 + 2 * cc) : (8 + 2 * cc);
            int iv = (int)st[col];
            Bb[r * PQ + e] = (w < 8) ? __ldg(p.suit + iv * 8 + d)
                                     : __ldg(p.rank + iv * 8 + d);
        }
    }
    __syncwarp();

    // board MLP: B -> B -> B -> C[64:144]
    dense_layer<80, 80, true >(g_wpk + 3072, p.bb1, Bb, PQ, Bb, PQ, g, t, lane);
    dense_layer<80, 80, true >(g_wpk + 4672, p.bb2, Bb, PQ, Bb, PQ, g, t, lane);
    dense_layer<80, 80, false>(g_wpk + 6272, p.bb3, Bb, PQ, Cb + 64, PW, g, t, lane);

    // hb MLP: C(144) -> C(144) -> C[0:64] -> C[0:64]   (all in-place)
    dense_layer<144,144, true >(g_wpk + 7872,  p.cb1, Cb, PW, Cb, PW, g, t, lane);
    dense_layer<144, 64, true >(g_wpk + 13056, p.cb2, Cb, PW, Cb, PW, g, t, lane);
    dense_layer< 64, 64, false>(g_wpk + 15360, p.cb3, Cb, PW, Cb, PW, g, t, lane);

    // ---------- output epilogue (warp-private; no sync needed) ----------
    const float* tabs[6] = { p.pos, p.action, p.active, p.street, p.nump, p.blind };
#pragma unroll 1
    for (int r = 0; r < 16; r++) {
        int row = row0 + r;
        if (row >= p.nrows) continue;
        float* orow = p.out + (size_t)row * 312;
        const float* st = p.state + (size_t)row * 50;
        const float* Crow = Cb + r * PW;
        for (int tt = lane; tt < 312; tt += 32) {
            float v;
            if (tt < 64) {
                v = Crow[tt];
            } else {
                int s = (tt - 64) >> 3, d = (tt - 64) & 7;
                int kind = c_kind[s], col = c_col[s];
                if (kind == 6) {
                    float sc = st[c_scol[col]];
                    int w = c_widx[col];
                    v = fmaf(sc, __ldg(p.sW + w * 8 + d), __ldg(p.sb + w * 8 + d));
                } else {
                    int iv = (int)st[col];
                    v = __ldg(tabs[kind] + iv * 8 + d);
                }
            }
            orow[tt] = v;
        }
    }
}

extern "C" void kernel_launch(void* const* d_in, const int* in_sizes, int n_in,
                              void* d_out, int out_size)
{
    Params p;
    p.state  = (const float*)d_in[0];
    p.suit   = (const float*)d_in[1];
    p.rank   = (const float*)d_in[2];
    p.hW1 = (const float*)d_in[3];  p.hb1 = (const float*)d_in[4];
    p.hW2 = (const float*)d_in[5];  p.hb2 = (const float*)d_in[6];
    p.hW3 = (const float*)d_in[7];  p.hb3 = (const float*)d_in[8];
    p.bW1 = (const float*)d_in[9];  p.bb1 = (const float*)d_in[10];
    p.bW2 = (const float*)d_in[11]; p.bb2 = (const float*)d_in[12];
    p.bW3 = (const float*)d_in[13]; p.bb3 = (const float*)d_in[14];
    p.cW1 = (const float*)d_in[15]; p.cb1 = (const float*)d_in[16];
    p.cW2 = (const float*)d_in[17]; p.cb2 = (const float*)d_in[18];
    p.cW3 = (const float*)d_in[19]; p.cb3 = (const float*)d_in[20];
    p.pos    = (const float*)d_in[21];
    p.action = (const float*)d_in[22];
    p.active = (const float*)d_in[23];
    p.street = (const float*)d_in[24];
    p.nump   = (const float*)d_in[25];
    p.blind  = (const float*)d_in[26];
    p.sW     = (const float*)d_in[27];
    p.sb     = (const float*)d_in[28];
    p.out    = (float*)d_out;
    p.nrows  = out_size / 312;

    pack_kernel<<<64, 256>>>(p);

    size_t smem_bytes = (size_t)NWARPS * WSZ * sizeof(float);
    cudaFuncSetAttribute(preproc_kernel, cudaFuncAttributeMaxDynamicSharedMemorySize,
                         (int)smem_bytes);
    int grid = (p.nrows + TM - 1) / TM;
    preproc_kernel<<<grid, NTHREADS, smem_bytes>>>(p);
}

// round 9
// speedup vs baseline: 4.3215x; 1.5375x over previous
#include <cuda_runtime.h>
#include <cuda_fp16.h>
#include <cstdint>

#define NWARPS    4
#define NTHREADS  (NWARPS * 32)
#define TM        (NWARPS * 16)     // 64 rows per CTA

// Packed fp16 hi/lo B-fragments. Per (layer,kt16,nt8,lane): uint4 =
// {bh0(k=2t,2t+1), bh1(k=2t+8,2t+9), bl0, bl1} for col n0+g. 16384 uint4 = 256KB.
__device__ uint4 g_wpk[16384];

// layer tables (pack kernel): NT=N/8, block cumsum, uint4 offset
__constant__ int c_NT[9]   = {8,8,8,10,10,10,18,8,8};
__constant__ int c_bcum[10]= {0,32,64,96,146,196,246,408,480,512};
__constant__ int c_u4off[9]= {0,1024,2048,3072,4672,6272,7872,13056,15360};

// Epilogue segment descriptors (31 segments of 8 after the 64 hb outputs)
__constant__ int c_kind[31] = {3,0,2,2,2,2,2,0,0,0,0,0,6,6,6,6,0,1,5,6,1,0,5,4,0,6,6,6,6,6,6};
__constant__ int c_col[31]  = {18,20,22,23,24,25,26,27,28,29,30,31,0,1,2,3,35,36,37,4,32,33,34,19,38,5,6,7,8,9,10};
__constant__ int c_scol[11] = {40,41,42,43,39,44,45,46,47,48,49};
__constant__ int c_widx[11] = {0,2,3,5,1,4,4,4,4,4,4};

struct Params {
    const float *state;
    const float *suit, *rank;
    const float *hW1,*hb1,*hW2,*hb2,*hW3,*hb3;
    const float *bW1,*bb1,*bW2,*bb2,*bW3,*bb3;
    const float *cW1,*cb1,*cW2,*cb2,*cW3,*cb3;
    const float *pos,*action,*active,*street,*nump,*blind;
    const float *sW,*sb;
    float *out;
    int nrows;
};

__device__ __forceinline__ float leaky(float v) { return v > 0.0f ? v : 0.01f * v; }

__device__ __forceinline__ uint32_t h2bits(__half2 h) {
    return *reinterpret_cast<uint32_t*>(&h);
}

// split (x,y) into packed fp16 hi and lo half2 bit patterns
__device__ __forceinline__ void split2(float x, float y, uint32_t& hi, uint32_t& lo) {
    __half2 h = __floats2half2_rn(x, y);
    float2 hf = __half22float2(h);
    __half2 l = __floats2half2_rn(x - hf.x, y - hf.y);
    hi = h2bits(h);
    lo = h2bits(l);
}

__device__ __forceinline__ void mma16(float (&c)[4],
                                      uint32_t a0, uint32_t a1, uint32_t a2, uint32_t a3,
                                      uint32_t b0, uint32_t b1)
{
    asm volatile("mma.sync.aligned.m16n8k16.row.col.f32.f16.f16.f32 "
                 "{%0,%1,%2,%3}, {%4,%5,%6,%7}, {%8,%9}, {%0,%1,%2,%3};\n"
                 : "+f"(c[0]), "+f"(c[1]), "+f"(c[2]), "+f"(c[3])
                 : "r"(a0), "r"(a1), "r"(a2), "r"(a3), "r"(b0), "r"(b1));
}

// ---------------- weight packing kernel (once per launch) ----------------
__global__ void pack_kernel(Params p)
{
    int tid = blockIdx.x * blockDim.x + threadIdx.x;
    if (tid >= 16384) return;
    int bid = tid >> 5, lane = tid & 31;
    int l = 0;
    while (bid >= c_bcum[l + 1]) l++;
    int NT = c_NT[l];
    int N  = NT * 8;
    int b  = bid - c_bcum[l];
    int kt = b / NT, nt = b % NT;
    int g = lane >> 2, t = lane & 3;
    const float* W;
    switch (l) {
        case 0: W = p.hW1; break;  case 1: W = p.hW2; break;  case 2: W = p.hW3; break;
        case 3: W = p.bW1; break;  case 4: W = p.bW2; break;  case 5: W = p.bW3; break;
        case 6: W = p.cW1; break;  case 7: W = p.cW2; break;  default: W = p.cW3; break;
    }
    int k0 = kt * 16, n = nt * 8 + g;
    float w00 = W[(k0 + 2*t)     * N + n];
    float w01 = W[(k0 + 2*t + 1) * N + n];
    float w10 = W[(k0 + 8 + 2*t)     * N + n];
    float w11 = W[(k0 + 8 + 2*t + 1) * N + n];
    uint4 v;
    split2(w00, w01, v.x, v.z);
    split2(w10, w11, v.y, v.w);
    g_wpk[c_u4off[l] + b * 32 + lane] = v;
}

// ---------------- register-chained dense layer ----------------
// Consumes A-frags ah/al (fp16 hi/lo, kt-tiles 0..KT-1), emits the NEXT layer's
// A-frags into oh/ol at kt slots OFF..OFF+NT/2-1. May alias (all reads precede writes).
template <int KT, int NT, bool ACT, int IKT, int OKT, int OFF>
__device__ __forceinline__ void layer_mid(const uint4* __restrict__ Wp,
                                          const float* __restrict__ bg,
                                          uint32_t (&ah)[IKT][4], uint32_t (&al)[IKT][4],
                                          uint32_t (&oh)[OKT][4], uint32_t (&ol)[OKT][4],
                                          int lane, int t)
{
    float acc[NT][4];
#pragma unroll
    for (int nt = 0; nt < NT; nt++) {
        acc[nt][0] = 0.f; acc[nt][1] = 0.f; acc[nt][2] = 0.f; acc[nt][3] = 0.f;
    }
    const uint4* wl = Wp + lane;
#pragma unroll
    for (int kt = 0; kt < KT; kt++) {
#pragma unroll
        for (int nt = 0; nt < NT; nt++) {
            uint4 w = __ldg(wl + (kt * NT + nt) * 32);
            mma16(acc[nt], ah[kt][0], ah[kt][1], ah[kt][2], ah[kt][3], w.x, w.y);
            mma16(acc[nt], al[kt][0], al[kt][1], al[kt][2], al[kt][3], w.x, w.y);
            mma16(acc[nt], ah[kt][0], ah[kt][1], ah[kt][2], ah[kt][3], w.z, w.w);
        }
    }
#pragma unroll
    for (int nt = 0; nt < NT; nt++) {
        float2 bb = __ldg((const float2*)(bg + nt * 8 + 2 * t));
        float v0 = acc[nt][0] + bb.x;
        float v1 = acc[nt][1] + bb.y;
        float v2 = acc[nt][2] + bb.x;
        float v3 = acc[nt][3] + bb.y;
        if (ACT) { v0 = leaky(v0); v1 = leaky(v1); v2 = leaky(v2); v3 = leaky(v3); }
        const int j = OFF + (nt >> 1);
        const int h = (nt & 1) * 2;
        split2(v0, v1, oh[j][h],     ol[j][h]);
        split2(v2, v3, oh[j][h + 1], ol[j][h + 1]);
    }
}

// Final layer: emit raw f32 accumulators (bias added by caller at store time).
template <int KT, int IKT>
__device__ __forceinline__ void layer_last(const uint4* __restrict__ Wp,
                                           uint32_t (&ah)[IKT][4], uint32_t (&al)[IKT][4],
                                           float (&acc)[8][4], int lane)
{
#pragma unroll
    for (int nt = 0; nt < 8; nt++) {
        acc[nt][0] = 0.f; acc[nt][1] = 0.f; acc[nt][2] = 0.f; acc[nt][3] = 0.f;
    }
    const uint4* wl = Wp + lane;
#pragma unroll
    for (int kt = 0; kt < KT; kt++) {
#pragma unroll
        for (int nt = 0; nt < 8; nt++) {
            uint4 w = __ldg(wl + (kt * 8 + nt) * 32);
            mma16(acc[nt], ah[kt][0], ah[kt][1], ah[kt][2], ah[kt][3], w.x, w.y);
            mma16(acc[nt], al[kt][0], al[kt][1], al[kt][2], al[kt][3], w.x, w.y);
            mma16(acc[nt], ah[kt][0], ah[kt][1], ah[kt][2], ah[kt][3], w.z, w.w);
        }
    }
}

__global__ void __launch_bounds__(NTHREADS, 3)
preproc_kernel(Params p)
{
    const int warp = threadIdx.x >> 5;
    const int lane = threadIdx.x & 31;
    const int g = lane >> 2, t = lane & 3;
    const int row0 = blockIdx.x * TM + warp * 16;

    const int rg  = min(row0 + g,     p.nrows - 1);
    const int rg8 = min(row0 + g + 8, p.nrows - 1);
    const float* st0 = p.state + (size_t)rg  * 50;
    const float* st1 = p.state + (size_t)rg8 * 50;

    uint32_t CH[9][4], CL[9][4];     // concat / hb-chain frags (144 cols = 9 kt)

    // ---------- hand: gather frags + 64->64->64->64 chain -> CH[0..3] ----------
    {
        uint32_t G[4][4], Gl[4][4];
#pragma unroll
        for (int c = 0; c < 4; c++) {
            int s0 = (int)__ldg(st0 + 2 * c + 1), r0i = (int)__ldg(st0 + 2 * c);
            int s1 = (int)__ldg(st1 + 2 * c + 1), r1i = (int)__ldg(st1 + 2 * c);
            float2 e;
            e = __ldg((const float2*)(p.suit + s0  * 8 + 2 * t)); split2(e.x, e.y, G[c][0], Gl[c][0]);
            e = __ldg((const float2*)(p.suit + s1  * 8 + 2 * t)); split2(e.x, e.y, G[c][1], Gl[c][1]);
            e = __ldg((const float2*)(p.rank + r0i * 8 + 2 * t)); split2(e.x, e.y, G[c][2], Gl[c][2]);
            e = __ldg((const float2*)(p.rank + r1i * 8 + 2 * t)); split2(e.x, e.y, G[c][3], Gl[c][3]);
        }
        layer_mid<4, 8, true , 4, 4, 0>(g_wpk + 0,    p.hb1, G, Gl, G, Gl, lane, t);
        layer_mid<4, 8, true , 4, 4, 0>(g_wpk + 1024, p.hb2, G, Gl, G, Gl, lane, t);
        layer_mid<4, 8, false, 4, 9, 0>(g_wpk + 2048, p.hb3, G, Gl, CH, CL, lane, t);
    }

    // ---------- board: gather frags + 80->80->80->80 chain -> CH[4..8] ----------
    {
        uint32_t Bd[5][4], Bl[5][4];
#pragma unroll
        for (int c = 0; c < 5; c++) {
            int s0 = (int)__ldg(st0 + 9 + 2 * c), r0i = (int)__ldg(st0 + 8 + 2 * c);
            int s1 = (int)__ldg(st1 + 9 + 2 * c), r1i = (int)__ldg(st1 + 8 + 2 * c);
            float2 e;
            e = __ldg((const float2*)(p.suit + s0  * 8 + 2 * t)); split2(e.x, e.y, Bd[c][0], Bl[c][0]);
            e = __ldg((const float2*)(p.suit + s1  * 8 + 2 * t)); split2(e.x, e.y, Bd[c][1], Bl[c][1]);
            e = __ldg((const float2*)(p.rank + r0i * 8 + 2 * t)); split2(e.x, e.y, Bd[c][2], Bl[c][2]);
            e = __ldg((const float2*)(p.rank + r1i * 8 + 2 * t)); split2(e.x, e.y, Bd[c][3], Bl[c][3]);
        }
        layer_mid<5, 10, true , 5, 5, 0>(g_wpk + 3072, p.bb1, Bd, Bl, Bd, Bl, lane, t);
        layer_mid<5, 10, true , 5, 5, 0>(g_wpk + 4672, p.bb2, Bd, Bl, Bd, Bl, lane, t);
        layer_mid<5, 10, false, 5, 9, 4>(g_wpk + 6272, p.bb3, Bd, Bl, CH, CL, lane, t);
    }

    // ---------- hb: 144->144->64->64 (all register-chained, in-place) ----------
    layer_mid<9, 18, true, 9, 9, 0>(g_wpk + 7872,  p.cb1, CH, CL, CH, CL, lane, t);
    layer_mid<9,  8, true, 9, 9, 0>(g_wpk + 13056, p.cb2, CH, CL, CH, CL, lane, t);
    float accF[8][4];
    layer_last<4, 9>(g_wpk + 15360, CH, CL, accF, lane);

    // ---------- store hb result (cols 0..63) ----------
    {
        float2 bb[8];
#pragma unroll
        for (int nt = 0; nt < 8; nt++)
            bb[nt] = __ldg((const float2*)(p.cb3 + nt * 8 + 2 * t));
        if (row0 + g < p.nrows) {
            float* o = p.out + (size_t)(row0 + g) * 312;
#pragma unroll
            for (int nt = 0; nt < 8; nt++)
                *(float2*)(o + nt * 8 + 2 * t) =
                    make_float2(accF[nt][0] + bb[nt].x, accF[nt][1] + bb[nt].y);
        }
        if (row0 + g + 8 < p.nrows) {
            float* o = p.out + (size_t)(row0 + g + 8) * 312;
#pragma unroll
            for (int nt = 0; nt < 8; nt++)
                *(float2*)(o + nt * 8 + 2 * t) =
                    make_float2(accF[nt][2] + bb[nt].x, accF[nt][3] + bb[nt].y);
        }
    }

    // ---------- aux epilogue: cols 64..311 from state ----------
    const float* tabs[6] = { p.pos, p.action, p.active, p.street, p.nump, p.blind };
#pragma unroll 1
    for (int r = 0; r < 16; r++) {
        int row = row0 + r;
        if (row >= p.nrows) continue;
        float* orow = p.out + (size_t)row * 312;
        const float* st = p.state + (size_t)row * 50;
        for (int tt = lane; tt < 248; tt += 32) {
            int s = tt >> 3, d = tt & 7;
            int kind = c_kind[s], col = c_col[s];
            float v;
            if (kind == 6) {
                float sc = st[c_scol[col]];
                int w = c_widx[col];
                v = fmaf(sc, __ldg(p.sW + w * 8 + d), __ldg(p.sb + w * 8 + d));
            } else {
                int iv = (int)st[col];
                v = __ldg(tabs[kind] + iv * 8 + d);
            }
            orow[64 + tt] = v;
        }
    }
}

extern "C" void kernel_launch(void* const* d_in, const int* in_sizes, int n_in,
                              void* d_out, int out_size)
{
    Params p;
    p.state  = (const float*)d_in[0];
    p.suit   = (const float*)d_in[1];
    p.rank   = (const float*)d_in[2];
    p.hW1 = (const float*)d_in[3];  p.hb1 = (const float*)d_in[4];
    p.hW2 = (const float*)d_in[5];  p.hb2 = (const float*)d_in[6];
    p.hW3 = (const float*)d_in[7];  p.hb3 = (const float*)d_in[8];
    p.bW1 = (const float*)d_in[9];  p.bb1 = (const float*)d_in[10];
    p.bW2 = (const float*)d_in[11]; p.bb2 = (const float*)d_in[12];
    p.bW3 = (const float*)d_in[13]; p.bb3 = (const float*)d_in[14];
    p.cW1 = (const float*)d_in[15]; p.cb1 = (const float*)d_in[16];
    p.cW2 = (const float*)d_in[17]; p.cb2 = (const float*)d_in[18];
    p.cW3 = (const float*)d_in[19]; p.cb3 = (const float*)d_in[20];
    p.pos    = (const float*)d_in[21];
    p.action = (const float*)d_in[22];
    p.active = (const float*)d_in[23];
    p.street = (const float*)d_in[24];
    p.nump   = (const float*)d_in[25];
    p.blind  = (const float*)d_in[26];
    p.sW     = (const float*)d_in[27];
    p.sb     = (const float*)d_in[28];
    p.out    = (float*)d_out;
    p.nrows  = out_size / 312;

    pack_kernel<<<64, 256>>>(p);

    int grid = (p.nrows + TM - 1) / TM;
    preproc_kernel<<<grid, NTHREADS>>>(p);
}